// round 15
// baseline (speedup 1.0000x reference)
#include <cuda_runtime.h>
#include <cuda_bf16.h>

// Problem constants (from reference_code)
#define BATCH    16384
#define N_SPARSE 26
#define N_DENSE  13
#define VOCAB    100000
#define EMB      64

// sm_103 ptxas: .L2::evict_last is only legal on 256-bit loads (.v8.b32).
// Each lane loads a 32B chunk of an embedding row with the evict-last hint so
// the ~112MB table working set can stay resident in the 126MB L2 across the
// harness's graph replays.
__device__ __forceinline__ void ldg_el_v8(const float* p, float* r) {
    asm volatile("ld.global.L2::evict_last.v8.b32 {%0,%1,%2,%3,%4,%5,%6,%7}, [%8];"
                 : "=f"(r[0]), "=f"(r[1]), "=f"(r[2]), "=f"(r[3]),
                   "=f"(r[4]), "=f"(r[5]), "=f"(r[6]), "=f"(r[7])
                 : "l"(p));
}

// One warp per batch row.
// Lane layout for the emb2 gather: g = lane>>3 (field slot, 4 per iter),
// c = lane&7 (32B chunk within the 256B row). 7 iterations cover 26 fields.
__global__ __launch_bounds__(256)
void fm_mtl_kernel(const int*   __restrict__ sparse,   // [B, 26]
                   const float* __restrict__ dense,    // [B, 13]
                   const float* __restrict__ emb1,     // [26, V, 1]
                   const float* __restrict__ emb2,     // [26, V, 64]
                   const float* __restrict__ W_dense,  // [13, 1]
                   const float* __restrict__ b_dense,  // [1]
                   const float* __restrict__ W_finish, // [1,1]
                   const float* __restrict__ b_finish, // [1]
                   const float* __restrict__ W_like,   // [1,1]
                   const float* __restrict__ b_like,   // [1]
                   float*       __restrict__ out)      // [2*B]: finish | like
{
    const int warp = (blockIdx.x * blockDim.x + threadIdx.x) >> 5;
    const int lane = threadIdx.x & 31;
    if (warp >= BATCH) return;
    const int row = warp;

    // ---- load this row's 26 indices into lanes 0..25 (streaming) ----
    int myidx = 0;
    if (lane < N_SPARSE) myidx = __ldcs(&sparse[row * N_SPARSE + lane]);

    // ---- first-order partials (ride along on low lanes) ----
    float fo = 0.f;
    if (lane < N_SPARSE)
        fo = __ldg(&emb1[(unsigned)lane * VOCAB + (unsigned)myidx]);
    if (lane < N_DENSE)
        fo += __ldcs(&dense[row * N_DENSE + lane]) * __ldg(&W_dense[lane]);

    // ---- second order gather: 7 iterations x 4 fields, 32B per lane ----
    const int g = lane >> 3;   // field slot within iteration
    const int c = lane & 7;    // 32B chunk within the row

    float s[8], q[8];
    #pragma unroll
    for (int j = 0; j < 8; j++) { s[j] = 0.f; q[j] = 0.f; }

    #pragma unroll
    for (int t = 0; t < 7; t++) {
        const int f = t * 4 + g;                 // field handled by this lane
        const bool act = (f < N_SPARSE);
        const int idx = __shfl_sync(0xffffffffu, myidx, act ? f : 0);
        if (act) {
            // float offset: (f*V + idx)*64 + c*8   (max ~166M floats, fits u32)
            const unsigned off =
                ((unsigned)(f * VOCAB) + (unsigned)idx) * EMB + (unsigned)(c * 8);
            float v[8];
            ldg_el_v8(emb2 + off, v);
            #pragma unroll
            for (int j = 0; j < 8; j++) {
                s[j] += v[j];
                q[j] += v[j] * v[j];
            }
        }
    }

    // Combine the 4 field-groups (lanes g=0..3 share chunk c) BEFORE squaring:
    // after this every lane holds the full-field sum s_e and q_e for its 8
    // elements e = c*8+j, replicated across the 4 groups.
    #pragma unroll
    for (int j = 0; j < 8; j++) {
        s[j] += __shfl_xor_sync(0xffffffffu, s[j], 8);
        q[j] += __shfl_xor_sync(0xffffffffu, q[j], 8);
        s[j] += __shfl_xor_sync(0xffffffffu, s[j], 16);
        q[j] += __shfl_xor_sync(0xffffffffu, q[j], 16);
    }

    float part = 0.f;
    #pragma unroll
    for (int j = 0; j < 8; j++)
        part += s[j] * s[j] - q[j];
    // part is replicated x4 across field-groups; warp-sum counts each chunk 4
    // times, so weight by 0.5/4 = 0.125 to get 0.5 * sum_e(s^2 - q).
    float r = fo + 0.125f * part;
    #pragma unroll
    for (int o = 16; o; o >>= 1)
        r += __shfl_xor_sync(0xffffffffu, r, o);

    if (lane == 0) {
        const float logit = r + __ldg(b_dense);
        const float zf = logit * __ldg(W_finish) + __ldg(b_finish);
        const float zl = logit * __ldg(W_like)   + __ldg(b_like);
        out[row]         = 1.f / (1.f + __expf(-zf));
        out[BATCH + row] = 1.f / (1.f + __expf(-zl));
    }
}

extern "C" void kernel_launch(void* const* d_in, const int* in_sizes, int n_in,
                              void* d_out, int out_size)
{
    const int*   sparse   = (const int*)  d_in[0];
    const float* dense    = (const float*)d_in[1];
    const float* emb1     = (const float*)d_in[2];
    const float* emb2     = (const float*)d_in[3];
    const float* W_dense  = (const float*)d_in[4];
    const float* b_dense  = (const float*)d_in[5];
    const float* W_finish = (const float*)d_in[6];
    const float* b_finish = (const float*)d_in[7];
    const float* W_like   = (const float*)d_in[8];
    const float* b_like   = (const float*)d_in[9];
    float* out = (float*)d_out;

    const int rows_per_block = 256 / 32;
    const int grid = (BATCH + rows_per_block - 1) / rows_per_block;  // 2048
    fm_mtl_kernel<<<grid, 256>>>(sparse, dense, emb1, emb2,
                                 W_dense, b_dense, W_finish, b_finish,
                                 W_like, b_like, out);
}